// round 7
// baseline (speedup 1.0000x reference)
#include <cuda_runtime.h>
#include <cstdint>

// Problem constants
#define BB 4
#define SS 4096
#define DD 2048
#define LL 3
#define TRIPLE (3 * DD)
#define MTOT (BB * SS)          // 16384

// GEMM tiling: CTA 128x128, 128 threads (4 warps 2x2), warp tile 64x64,
// BK=32, 3-stage cp.async, 2 CTAs per SM.
// A smem: [128][40] (32 cols + 8 pad), k permuted within 8-blocks.
// B smem: [16][264] pair-interleaved rows: row (kb*4+p) holds logical
//         k = kb*8+p (h=0) and kb*8+p+4 (h=1) interleaved along n.
#define BM 128
#define BN 128
#define BK 32
#define NSTAGE 3
#define AST 40
#define BST 264
#define A_SM (BM * AST)         // 5120 floats
#define B_SM (16 * BST)         // 4224 floats
#define STG_FLT (A_SM + B_SM)   // 9344 floats
#define SMEM_BYTES (NSTAGE * STG_FLT * 4)   // 112128 B

// Scratch (__device__ globals: allocation-free rule)
__device__ float g_BCx[(size_t)BB * SS * TRIPLE];   // GEMM1 C (natural layout)
__device__ float g_y[(size_t)BB * SS * DD];         // GEMM2 A (tf32, k-permuted)
__device__ float g_xc[(size_t)BB * SS * DD];        // x (tf32, k-permuted)
__device__ float g_Win[(size_t)DD * TRIPLE];        // W_in  pair-interleaved [K/2][2N]
__device__ float g_Wout[(size_t)DD * DD];           // W_out pair-interleaved

__device__ __forceinline__ float f2tf32(float x) {
    float r;
    asm("cvt.rna.tf32.f32 %0, %1;" : "=f"(r) : "f"(x));
    return r;
}

__device__ __forceinline__ uint32_t smem_u32(const void* p) {
    uint32_t a;
    asm("{ .reg .u64 t; cvta.to.shared.u64 t, %1; cvt.u32.u64 %0, t; }" : "=r"(a) : "l"(p));
    return a;
}

#define CP_ASYNC16(dst, src) \
    asm volatile("cp.async.cg.shared.global [%0], [%1], 16;" :: "r"(dst), "l"(src))
#define CP_COMMIT() asm volatile("cp.async.commit_group;" ::: "memory")
#define CP_WAIT1()  asm volatile("cp.async.wait_group 1;" ::: "memory")

__device__ __forceinline__ void mma_tf32(float c[4], const uint32_t a[4], const uint32_t b[2]) {
    asm volatile(
        "mma.sync.aligned.m16n8k8.row.col.f32.tf32.tf32.f32 "
        "{%0,%1,%2,%3}, {%4,%5,%6,%7}, {%8,%9}, {%0,%1,%2,%3};"
        : "+f"(c[0]), "+f"(c[1]), "+f"(c[2]), "+f"(c[3])
        : "r"(a[0]), "r"(a[1]), "r"(a[2]), "r"(a[3]), "r"(b[0]), "r"(b[1]));
}

// ---------------------------------------------------------------------------
// TF32 mma.sync GEMM on permuted inputs.
// A: [M][K] row-major, k permuted within 8-blocks: phys 2l <- logical l,
//    phys 2l+1 <- logical l+4 (l = k&3 ... within each 8-block).
// B: [K/2][2N]: row (kb*4+p), col 2n+h = W[kb*8+p+4h][n]  (same permutation).
// C: [M][N] natural.
// ---------------------------------------------------------------------------
__global__ __launch_bounds__(128, 2)
void tf32_gemm(const float* __restrict__ A, const float* __restrict__ B,
               float* __restrict__ C, int N, int K) {
    extern __shared__ float sm[];
    const uint32_t smb = smem_u32(sm);

    const int tid    = threadIdx.x;
    const int wid    = tid >> 5;
    const int lane   = tid & 31;
    const int warp_m = wid >> 1;      // 0..1
    const int warp_n = wid & 1;       // 0..1
    const int lr     = lane >> 2;     // 0..7
    const int lc     = lane & 3;      // 0..3

    const int brow = blockIdx.y * BM;
    const int bcol = blockIdx.x * BN;

    const float* Ap = A + (size_t)brow * K;
    const float* Bp = B + 2 * (size_t)bcol;
    const size_t brs = 2 * (size_t)N;         // B row stride (floats)

    // cp.async coords (128 threads)
    const int arow0 = tid >> 3;               // + i*16
    const int akc   = (tid & 7) * 4;          // 0..28
    const int brw   = tid >> 3;               // B phys row 0..15
    const int bcc   = (tid & 7) * 4;          // + i*32 floats

    auto issue = [&](int kt, int buf) {
        uint32_t as = smb + (uint32_t)buf * STG_FLT * 4;
        uint32_t bs = as + A_SM * 4;
        #pragma unroll
        for (int i = 0; i < 8; i++) {
            int m = arow0 + i * 16;
            CP_ASYNC16(as + (uint32_t)(m * AST + akc) * 4,
                       Ap + (size_t)m * K + kt * BK + akc);
        }
        const float* bsrc = Bp + (size_t)(16 * kt + brw) * brs;
        #pragma unroll
        for (int i = 0; i < 8; i++) {
            int c = bcc + i * 32;
            CP_ASYNC16(bs + (uint32_t)(brw * BST + c) * 4, bsrc + c);
        }
    };

    float acc[4][8][4];
    #pragma unroll
    for (int mi = 0; mi < 4; mi++)
        #pragma unroll
        for (int ni = 0; ni < 8; ni++)
            #pragma unroll
            for (int t = 0; t < 4; t++)
                acc[mi][ni][t] = 0.0f;

    const int NK = K / BK;

    issue(0, 0); CP_COMMIT();
    issue(1, 1); CP_COMMIT();

    int buf = 0;
    for (int kt = 0; kt < NK; kt++) {
        CP_WAIT1();
        __syncthreads();

        if (kt + 2 < NK) {
            int nbuf = buf + 2; if (nbuf >= NSTAGE) nbuf -= NSTAGE;
            issue(kt + 2, nbuf);
        }
        CP_COMMIT();

        const float* As = sm + (size_t)buf * STG_FLT;
        const float* Bs = As + A_SM;

        #pragma unroll
        for (int ks = 0; ks < 4; ks++) {
            uint32_t a[4][4];
            #pragma unroll
            for (int mi = 0; mi < 4; mi++) {
                const int r = warp_m * 64 + mi * 16 + lr;
                float2 v0 = *(const float2*)(As + r * AST + ks * 8 + 2 * lc);
                float2 v1 = *(const float2*)(As + (r + 8) * AST + ks * 8 + 2 * lc);
                a[mi][0] = __float_as_uint(v0.x);
                a[mi][2] = __float_as_uint(v0.y);
                a[mi][1] = __float_as_uint(v1.x);
                a[mi][3] = __float_as_uint(v1.y);
            }
            uint32_t b[8][2];
            #pragma unroll
            for (int ni = 0; ni < 8; ni++) {
                const int n = warp_n * 64 + ni * 8 + lr;
                float2 v = *(const float2*)(Bs + (ks * 4 + lc) * BST + 2 * n);
                b[ni][0] = __float_as_uint(v.x);
                b[ni][1] = __float_as_uint(v.y);
            }
            #pragma unroll
            for (int mi = 0; mi < 4; mi++)
                #pragma unroll
                for (int ni = 0; ni < 8; ni++)
                    mma_tf32(acc[mi][ni], a[mi], b[ni]);
        }

        if (++buf == NSTAGE) buf = 0;
    }

    // Epilogue
    #pragma unroll
    for (int mi = 0; mi < 4; mi++) {
        #pragma unroll
        for (int ni = 0; ni < 8; ni++) {
            const int r0 = brow + warp_m * 64 + mi * 16 + lr;
            const int c0 = bcol + warp_n * 64 + ni * 8 + lc * 2;
            *(float2*)(C + (size_t)r0 * N + c0)       = make_float2(acc[mi][ni][0], acc[mi][ni][1]);
            *(float2*)(C + (size_t)(r0 + 8) * N + c0) = make_float2(acc[mi][ni][2], acc[mi][ni][3]);
        }
    }
}

// ---------------------------------------------------------------------------
// x -> tf32 + k-permute within 8-blocks: phys float4#0 = (l0,l4,l1,l5),
// phys float4#1 = (l2,l6,l3,l7).
// ---------------------------------------------------------------------------
__global__ void cvt_perm_kernel(const float* __restrict__ in, float* __restrict__ out,
                                size_t n8) {
    size_t i = (size_t)blockIdx.x * blockDim.x + threadIdx.x;
    if (i >= n8) return;
    const float4* p = (const float4*)(in + i * 8);
    float4 lo = p[0], hi = p[1];
    float4 w0 = make_float4(f2tf32(lo.x), f2tf32(hi.x), f2tf32(lo.y), f2tf32(hi.y));
    float4 w1 = make_float4(f2tf32(lo.z), f2tf32(hi.z), f2tf32(lo.w), f2tf32(hi.w));
    float4* q = (float4*)(out + i * 8);
    q[0] = w0; q[1] = w1;
}

// ---------------------------------------------------------------------------
// W [K][N] -> pair-interleaved [K/2][2N]: out[kb*4+p][2n+h] = tf32(W[kb*8+p+4h][n])
// Block: one k-block (8 rows) x 256 n-cols. 256 threads.
// ---------------------------------------------------------------------------
__global__ void wtrans_kernel(const float* __restrict__ in, float* __restrict__ out,
                              int N) {
    __shared__ float s[8][257];
    const int kb = blockIdx.y;
    const int n0 = blockIdx.x * 256;
    const int tid = threadIdx.x;

    #pragma unroll
    for (int j = 0; j < 8; j++)
        s[j][tid] = f2tf32(in[(size_t)(kb * 8 + j) * N + n0 + tid]);
    __syncthreads();

    const int p  = tid >> 6;        // 0..3
    const int j0 = tid & 63;
    #pragma unroll
    for (int h = 0; h < 2; h++) {
        int j = j0 + h * 64;        // 0..127 (n-pair index)
        float4 v = make_float4(s[p][2 * j], s[p + 4][2 * j],
                               s[p][2 * j + 1], s[p + 4][2 * j + 1]);
        *(float4*)(out + (size_t)(kb * 4 + p) * (2 * N) + 2 * n0 + 4 * j) = v;
    }
}

// ---------------------------------------------------------------------------
// Fused: Bx = B_gate*x_proj; causal L=3 depthwise conv; y = tf32(C_gate*conv),
// written in k-permuted layout for GEMM2. 8 d's per thread.
// ---------------------------------------------------------------------------
__global__ void conv_gate_kernel(const float* __restrict__ conv_w,
                                 float* __restrict__ y) {
    const size_t total = (size_t)BB * SS * (DD / 8);
    size_t idx = (size_t)blockIdx.x * blockDim.x + threadIdx.x;
    if (idx >= total) return;

    const int    d8 = (int)(idx % (DD / 8));
    const size_t bs = idx / (DD / 8);
    const int    s  = (int)(bs % SS);
    const int    d  = d8 * 8;

    const float* bse = g_BCx + bs * TRIPLE;
    const float* bm1 = bse - TRIPLE;
    const float* bm2 = bse - 2 * TRIPLE;

    float o[8];
    #pragma unroll
    for (int j = 0; j < 8; j++) {
        const int dj = d + j;
        const float w0 = conv_w[dj * LL + 0];
        const float w1 = conv_w[dj * LL + 1];
        const float w2 = conv_w[dj * LL + 2];

        float bx_s  = bse[dj] * bse[2 * DD + dj];
        float bx_s1 = (s >= 1) ? bm1[dj] * bm1[2 * DD + dj] : 0.0f;
        float bx_s2 = (s >= 2) ? bm2[dj] * bm2[2 * DD + dj] : 0.0f;

        float conv = w2 * bx_s + w1 * bx_s1 + w0 * bx_s2;
        o[j] = f2tf32(bse[DD + dj] * conv);
    }
    // k-permuted write: phys (l0,l4,l1,l5) / (l2,l6,l3,l7)
    float4 w0 = make_float4(o[0], o[4], o[1], o[5]);
    float4 w1 = make_float4(o[2], o[6], o[3], o[7]);
    float4* q = (float4*)(y + bs * DD + d);
    q[0] = w0; q[1] = w1;
}

// ---------------------------------------------------------------------------
extern "C" void kernel_launch(void* const* d_in, const int* in_sizes, int n_in,
                              void* d_out, int out_size) {
    const float* x      = (const float*)d_in[0];
    const float* W_in   = (const float*)d_in[1];
    const float* conv_w = (const float*)d_in[2];
    const float* W_out  = (const float*)d_in[3];
    float*       out    = (float*)d_out;

    float *BCx, *y, *xc, *Win, *Wout;
    cudaGetSymbolAddress((void**)&BCx,  g_BCx);
    cudaGetSymbolAddress((void**)&y,    g_y);
    cudaGetSymbolAddress((void**)&xc,   g_xc);
    cudaGetSymbolAddress((void**)&Win,  g_Win);
    cudaGetSymbolAddress((void**)&Wout, g_Wout);

    cudaFuncSetAttribute(tf32_gemm, cudaFuncAttributeMaxDynamicSharedMemorySize, SMEM_BYTES);

    // Pre-passes: tf32 rounding + layout transforms
    {
        size_t n8 = (size_t)MTOT * DD / 8;
        cvt_perm_kernel<<<(unsigned)((n8 + 255) / 256), 256>>>(x, xc, n8);
        wtrans_kernel<<<dim3(TRIPLE / 256, DD / 8), 256>>>(W_in, Win, TRIPLE);
        wtrans_kernel<<<dim3(DD / 256, DD / 8), 256>>>(W_out, Wout, DD);
    }

    // GEMM1: BCx = x' @ W_in'   (16384 x 2048) @ (2048 x 6144)
    tf32_gemm<<<dim3(TRIPLE / BN, MTOT / BM), 128, SMEM_BYTES>>>(xc, Win, BCx, TRIPLE, DD);

    // Conv + gates -> y (tf32, k-permuted)
    {
        size_t total = (size_t)BB * SS * (DD / 8);
        conv_gate_kernel<<<(unsigned)((total + 255) / 256), 256>>>(conv_w, y);
    }

    // GEMM2: out = y @ W_out'   (16384 x 2048) @ (2048 x 2048)
    tf32_gemm<<<dim3(DD / BN, MTOT / BM), 128, SMEM_BYTES>>>(y, Wout, out, DD, DD);
}

// round 8
// speedup vs baseline: 1.5187x; 1.5187x over previous
#include <cuda_runtime.h>
#include <cstdint>

// Problem constants
#define BB 4
#define SS 4096
#define DD 2048
#define LL 3
#define TRIPLE (3 * DD)
#define MTOT (BB * SS)          // 16384

// GEMM tiling: CTA 128x128, 128 threads (4 warps 2x2), warp tile 64x64,
// BK=32, 3-stage cp.async, 2 CTAs per SM.
#define BM 128
#define BN 128
#define BK 32
#define NSTAGE 3
#define AST 36                  // A smem row stride (floats): 32 + 4 pad
#define BST 136                 // B smem row stride (floats): 128 + 8 pad
#define A_SM (BM * AST)         // 4608 floats
#define B_SM (BK * BST)         // 4352 floats
#define STG_FLT (A_SM + B_SM)   // 8960 floats
#define SMEM_BYTES (NSTAGE * STG_FLT * 4)   // 107520 B

// Scratch (__device__ globals: allocation-free rule)
__device__ float g_BCx[(size_t)BB * SS * TRIPLE];   // [b,s,3D] = [B_gate|C_gate|x_proj]
__device__ float g_y[(size_t)BB * SS * DD];         // GEMM2 A (tf32-rounded)
__device__ float g_xc[(size_t)BB * SS * DD];        // x tf32-rounded
__device__ float g_Win[(size_t)DD * TRIPLE];        // W_in  tf32-rounded
__device__ float g_Wout[(size_t)DD * DD];           // W_out tf32-rounded

__device__ __forceinline__ float f2tf32(float x) {
    float r;
    asm("cvt.rna.tf32.f32 %0, %1;" : "=f"(r) : "f"(x));
    return r;
}

__device__ __forceinline__ uint32_t smem_u32(const void* p) {
    uint32_t a;
    asm("{ .reg .u64 t; cvta.to.shared.u64 t, %1; cvt.u32.u64 %0, t; }" : "=r"(a) : "l"(p));
    return a;
}

#define CP_ASYNC16(dst, src) \
    asm volatile("cp.async.cg.shared.global [%0], [%1], 16;" :: "r"(dst), "l"(src))
#define CP_COMMIT() asm volatile("cp.async.commit_group;" ::: "memory")
#define CP_WAIT1()  asm volatile("cp.async.wait_group 1;" ::: "memory")

__device__ __forceinline__ void mma_tf32(float c[4], const uint32_t a[4], const uint32_t b[2]) {
    asm volatile(
        "mma.sync.aligned.m16n8k8.row.col.f32.tf32.tf32.f32 "
        "{%0,%1,%2,%3}, {%4,%5,%6,%7}, {%8,%9}, {%0,%1,%2,%3};"
        : "+f"(c[0]), "+f"(c[1]), "+f"(c[2]), "+f"(c[3])
        : "r"(a[0]), "r"(a[1]), "r"(a[2]), "r"(a[3]), "r"(b[0]), "r"(b[1]));
}

// ---------------------------------------------------------------------------
// TF32 mma.sync GEMM: C[M,N] = A[M,K] @ B[K,N], row-major fp32 (pre-rounded).
// 128 threads, warps 2x2, warp tile 64x64. M%128==0, N%128==0, K%32==0.
// Fragment double-buffering across ks steps hides LDS latency under HMMA.
// ---------------------------------------------------------------------------
__global__ __launch_bounds__(128, 2)
void tf32_gemm(const float* __restrict__ A, const float* __restrict__ B,
               float* __restrict__ C, int N, int K) {
    extern __shared__ float sm[];
    const uint32_t smb = smem_u32(sm);

    const int tid    = threadIdx.x;
    const int wid    = tid >> 5;
    const int lane   = tid & 31;
    const int warp_m = wid >> 1;      // 0..1
    const int warp_n = wid & 1;       // 0..1
    const int lr     = lane >> 2;     // 0..7
    const int lc     = lane & 3;      // 0..3

    const int brow = blockIdx.y * BM;
    const int bcol = blockIdx.x * BN;

    const float* Ap = A + (size_t)brow * K;
    const float* Bp = B + bcol;

    // cp.async coords (128 threads): A 128x32 = 1024 chunks (8/thread),
    // B 32x128 = 1024 chunks (8/thread)
    const int arow0 = tid >> 3;             // +i*16
    const int akc   = (tid & 7) * 4;
    const int brow0 = tid >> 5;             // +i*4
    const int bnc   = (tid & 31) * 4;

    auto issue = [&](int kt, int buf) {
        uint32_t as = smb + (uint32_t)buf * STG_FLT * 4;
        uint32_t bs = as + A_SM * 4;
        #pragma unroll
        for (int i = 0; i < 8; i++) {
            int m = arow0 + i * 16;
            CP_ASYNC16(as + (uint32_t)(m * AST + akc) * 4,
                       Ap + (size_t)m * K + kt * BK + akc);
        }
        #pragma unroll
        for (int i = 0; i < 8; i++) {
            int k = brow0 + i * 4;
            CP_ASYNC16(bs + (uint32_t)(k * BST + bnc) * 4,
                       Bp + (size_t)(kt * BK + k) * N + bnc);
        }
    };

    float acc[4][8][4];
    #pragma unroll
    for (int mi = 0; mi < 4; mi++)
        #pragma unroll
        for (int ni = 0; ni < 8; ni++)
            #pragma unroll
            for (int t = 0; t < 4; t++)
                acc[mi][ni][t] = 0.0f;

    const int NK = K / BK;

    issue(0, 0); CP_COMMIT();
    issue(1, 1); CP_COMMIT();

    // double-buffered fragments
    uint32_t a[2][4][4], b[2][8][4 / 2];

    auto load_frag = [&](const float* As, const float* Bs, int ks, int pb) {
        const int k0 = ks * 8;
        #pragma unroll
        for (int mi = 0; mi < 4; mi++) {
            const int base = (warp_m * 64 + mi * 16 + lr) * AST + k0 + lc;
            a[pb][mi][0] = __float_as_uint(As[base]);
            a[pb][mi][1] = __float_as_uint(As[base + 8 * AST]);
            a[pb][mi][2] = __float_as_uint(As[base + 4]);
            a[pb][mi][3] = __float_as_uint(As[base + 8 * AST + 4]);
        }
        #pragma unroll
        for (int ni = 0; ni < 8; ni++) {
            const int base = (k0 + lc) * BST + warp_n * 64 + ni * 8 + lr;
            b[pb][ni][0] = __float_as_uint(Bs[base]);
            b[pb][ni][1] = __float_as_uint(Bs[base + 4 * BST]);
        }
    };

    int buf = 0;
    for (int kt = 0; kt < NK; kt++) {
        CP_WAIT1();
        __syncthreads();

        if (kt + 2 < NK) {
            int nbuf = buf + 2; if (nbuf >= NSTAGE) nbuf -= NSTAGE;
            issue(kt + 2, nbuf);
        }
        CP_COMMIT();

        const float* As = sm + (size_t)buf * STG_FLT;
        const float* Bs = As + A_SM;

        load_frag(As, Bs, 0, 0);
        #pragma unroll
        for (int ks = 0; ks < 4; ks++) {
            const int cur = ks & 1;
            if (ks < 3) load_frag(As, Bs, ks + 1, cur ^ 1);
            #pragma unroll
            for (int mi = 0; mi < 4; mi++)
                #pragma unroll
                for (int ni = 0; ni < 8; ni++)
                    mma_tf32(acc[mi][ni], a[cur][mi], b[cur][ni]);
        }

        __syncthreads();
        if (++buf == NSTAGE) buf = 0;
    }

    // Epilogue
    #pragma unroll
    for (int mi = 0; mi < 4; mi++) {
        #pragma unroll
        for (int ni = 0; ni < 8; ni++) {
            const int r0 = brow + warp_m * 64 + mi * 16 + lr;
            const int c0 = bcol + warp_n * 64 + ni * 8 + lc * 2;
            *(float2*)(C + (size_t)r0 * N + c0)       = make_float2(acc[mi][ni][0], acc[mi][ni][1]);
            *(float2*)(C + (size_t)(r0 + 8) * N + c0) = make_float2(acc[mi][ni][2], acc[mi][ni][3]);
        }
    }
}

// ---------------------------------------------------------------------------
// Elementwise tf32 rounding (float4 vectorized)
// ---------------------------------------------------------------------------
__global__ void cvt_tf32_kernel(const float* __restrict__ in, float* __restrict__ out,
                                size_t n4) {
    size_t i = (size_t)blockIdx.x * blockDim.x + threadIdx.x;
    if (i >= n4) return;
    float4 v = ((const float4*)in)[i];
    v.x = f2tf32(v.x); v.y = f2tf32(v.y); v.z = f2tf32(v.z); v.w = f2tf32(v.w);
    ((float4*)out)[i] = v;
}

// ---------------------------------------------------------------------------
// Fused: Bx = B_gate*x_proj; causal L=3 depthwise conv; y = tf32(C_gate*conv)
// ---------------------------------------------------------------------------
__global__ void conv_gate_kernel(const float* __restrict__ conv_w,
                                 float* __restrict__ y) {
    const size_t total = (size_t)BB * SS * (DD / 4);
    size_t idx = (size_t)blockIdx.x * blockDim.x + threadIdx.x;
    if (idx >= total) return;

    const int    d4 = (int)(idx % (DD / 4));
    const size_t bs = idx / (DD / 4);
    const int    s  = (int)(bs % SS);
    const int    d  = d4 * 4;

    const float* bse = g_BCx + bs * TRIPLE;
    const float* bm1 = bse - TRIPLE;
    const float* bm2 = bse - 2 * TRIPLE;

    float out[4];
    #pragma unroll
    for (int j = 0; j < 4; j++) {
        const int dj = d + j;
        const float w0 = conv_w[dj * LL + 0];
        const float w1 = conv_w[dj * LL + 1];
        const float w2 = conv_w[dj * LL + 2];

        float bx_s  = bse[dj] * bse[2 * DD + dj];
        float bx_s1 = (s >= 1) ? bm1[dj] * bm1[2 * DD + dj] : 0.0f;
        float bx_s2 = (s >= 2) ? bm2[dj] * bm2[2 * DD + dj] : 0.0f;

        float conv = w2 * bx_s + w1 * bx_s1 + w0 * bx_s2;
        out[j] = f2tf32(bse[DD + dj] * conv);
    }
    *(float4*)(g_y + bs * DD + d) = *(float4*)out;
}

// ---------------------------------------------------------------------------
extern "C" void kernel_launch(void* const* d_in, const int* in_sizes, int n_in,
                              void* d_out, int out_size) {
    const float* x      = (const float*)d_in[0];
    const float* W_in   = (const float*)d_in[1];
    const float* conv_w = (const float*)d_in[2];
    const float* W_out  = (const float*)d_in[3];
    float*       out    = (float*)d_out;

    float *BCx, *y, *xc, *Win, *Wout;
    cudaGetSymbolAddress((void**)&BCx,  g_BCx);
    cudaGetSymbolAddress((void**)&y,    g_y);
    cudaGetSymbolAddress((void**)&xc,   g_xc);
    cudaGetSymbolAddress((void**)&Win,  g_Win);
    cudaGetSymbolAddress((void**)&Wout, g_Wout);

    cudaFuncSetAttribute(tf32_gemm, cudaFuncAttributeMaxDynamicSharedMemorySize, SMEM_BYTES);

    // Pre-round inputs to tf32 (rna) into scratch
    {
        size_t n4;
        n4 = (size_t)MTOT * DD / 4;
        cvt_tf32_kernel<<<(unsigned)((n4 + 255) / 256), 256>>>(x, xc, n4);
        n4 = (size_t)DD * TRIPLE / 4;
        cvt_tf32_kernel<<<(unsigned)((n4 + 255) / 256), 256>>>(W_in, Win, n4);
        n4 = (size_t)DD * DD / 4;
        cvt_tf32_kernel<<<(unsigned)((n4 + 255) / 256), 256>>>(W_out, Wout, n4);
    }

    // GEMM1: BCx = x' @ W_in'   (16384 x 2048) @ (2048 x 6144)
    tf32_gemm<<<dim3(TRIPLE / BN, MTOT / BM), 128, SMEM_BYTES>>>(xc, Win, BCx, TRIPLE, DD);

    // Conv + gates -> y (tf32-rounded)
    {
        size_t total = (size_t)BB * SS * (DD / 4);
        conv_gate_kernel<<<(unsigned)((total + 255) / 256), 256>>>(conv_w, y);
    }

    // GEMM2: out = y @ W_out'   (16384 x 2048) @ (2048 x 2048)
    tf32_gemm<<<dim3(DD / BN, MTOT / BM), 128, SMEM_BYTES>>>(y, Wout, out, DD, DD);
}

// round 9
// speedup vs baseline: 1.5315x; 1.0084x over previous
#include <cuda_runtime.h>
#include <cstdint>

// Problem constants
#define BB 4
#define SS 4096
#define DD 2048
#define LL 3
#define TRIPLE (3 * DD)
#define MTOT (BB * SS)          // 16384

// GEMM tiling: CTA 128x128, 128 threads (4 warps 2x2), warp tile 64x64,
// BK=32, 3-stage cp.async, 2 CTAs per SM. ONE barrier per k-tile.
#define BM 128
#define BN 128
#define BK 32
#define NSTAGE 3
#define AST 36                  // A smem row stride (floats): 32 + 4 pad
#define BST 136                 // B smem row stride (floats): 128 + 8 pad
#define A_SM (BM * AST)         // 4608 floats
#define B_SM (BK * BST)         // 4352 floats
#define STG_FLT (A_SM + B_SM)   // 8960 floats
#define SMEM_BYTES (NSTAGE * STG_FLT * 4)   // 107520 B

// Scratch (__device__ globals: allocation-free rule)
__device__ float g_BCx[(size_t)BB * SS * TRIPLE];   // [b,s,3D] = [B_gate|C_gate|x_proj]
__device__ float g_y[(size_t)BB * SS * DD];         // GEMM2 A (tf32-rounded)
__device__ float g_xc[(size_t)BB * SS * DD];        // x tf32-rounded
__device__ float g_Win[(size_t)DD * TRIPLE];        // W_in  tf32-rounded
__device__ float g_Wout[(size_t)DD * DD];           // W_out tf32-rounded

__device__ __forceinline__ float f2tf32(float x) {
    float r;
    asm("cvt.rna.tf32.f32 %0, %1;" : "=f"(r) : "f"(x));
    return r;
}

__device__ __forceinline__ uint32_t smem_u32(const void* p) {
    uint32_t a;
    asm("{ .reg .u64 t; cvta.to.shared.u64 t, %1; cvt.u32.u64 %0, t; }" : "=r"(a) : "l"(p));
    return a;
}

#define CP_ASYNC16(dst, src) \
    asm volatile("cp.async.cg.shared.global [%0], [%1], 16;" :: "r"(dst), "l"(src))
#define CP_COMMIT() asm volatile("cp.async.commit_group;" ::: "memory")
#define CP_WAIT1()  asm volatile("cp.async.wait_group 1;" ::: "memory")

__device__ __forceinline__ void mma_tf32(float c[4], const uint32_t a[4], const uint32_t b[2]) {
    asm volatile(
        "mma.sync.aligned.m16n8k8.row.col.f32.tf32.tf32.f32 "
        "{%0,%1,%2,%3}, {%4,%5,%6,%7}, {%8,%9}, {%0,%1,%2,%3};"
        : "+f"(c[0]), "+f"(c[1]), "+f"(c[2]), "+f"(c[3])
        : "r"(a[0]), "r"(a[1]), "r"(a[2]), "r"(a[3]), "r"(b[0]), "r"(b[1]));
}

// ---------------------------------------------------------------------------
// TF32 mma.sync GEMM: C[M,N] = A[M,K] @ B[K,N], row-major fp32 (pre-rounded).
// 128 threads, warps 2x2, warp tile 64x64. M%128==0, N%128==0, K%32==0.
// Single barrier per k-tile:
//  - RAW: each thread's cp.async.wait_group(1) before the barrier guarantees
//    its own chunks of buffer kt landed; barrier publishes all threads'.
//  - WAR: issuing into buffer (kt+2)%3 == (kt-1)%3 is safe because the top
//    barrier of iteration kt orders all reads from iteration kt-1 before it.
// ---------------------------------------------------------------------------
__global__ __launch_bounds__(128, 2)
void tf32_gemm(const float* __restrict__ A, const float* __restrict__ B,
               float* __restrict__ C, int N, int K) {
    extern __shared__ float sm[];
    const uint32_t smb = smem_u32(sm);

    const int tid    = threadIdx.x;
    const int wid    = tid >> 5;
    const int lane   = tid & 31;
    const int warp_m = wid >> 1;      // 0..1
    const int warp_n = wid & 1;       // 0..1
    const int lr     = lane >> 2;     // 0..7
    const int lc     = lane & 3;      // 0..3

    const int brow = blockIdx.y * BM;
    const int bcol = blockIdx.x * BN;

    const float* Ap = A + (size_t)brow * K;
    const float* Bp = B + bcol;

    // cp.async coords (128 threads): A 128x32 = 1024 chunks (8/thread),
    // B 32x128 = 1024 chunks (8/thread)
    const int arow0 = tid >> 3;             // +i*16
    const int akc   = (tid & 7) * 4;
    const int brow0 = tid >> 5;             // +i*4
    const int bnc   = (tid & 31) * 4;

    auto issue = [&](int kt, int buf) {
        uint32_t as = smb + (uint32_t)buf * STG_FLT * 4;
        uint32_t bs = as + A_SM * 4;
        #pragma unroll
        for (int i = 0; i < 8; i++) {
            int m = arow0 + i * 16;
            CP_ASYNC16(as + (uint32_t)(m * AST + akc) * 4,
                       Ap + (size_t)m * K + kt * BK + akc);
        }
        #pragma unroll
        for (int i = 0; i < 8; i++) {
            int k = brow0 + i * 4;
            CP_ASYNC16(bs + (uint32_t)(k * BST + bnc) * 4,
                       Bp + (size_t)(kt * BK + k) * N + bnc);
        }
    };

    float acc[4][8][4];
    #pragma unroll
    for (int mi = 0; mi < 4; mi++)
        #pragma unroll
        for (int ni = 0; ni < 8; ni++)
            #pragma unroll
            for (int t = 0; t < 4; t++)
                acc[mi][ni][t] = 0.0f;

    const int NK = K / BK;

    issue(0, 0); CP_COMMIT();
    issue(1, 1); CP_COMMIT();

    int buf = 0;
    for (int kt = 0; kt < NK; kt++) {
        CP_WAIT1();
        __syncthreads();

        if (kt + 2 < NK) {
            int nbuf = buf + 2; if (nbuf >= NSTAGE) nbuf -= NSTAGE;
            issue(kt + 2, nbuf);
        }
        CP_COMMIT();

        const float* As = sm + (size_t)buf * STG_FLT;
        const float* Bs = As + A_SM;

        #pragma unroll
        for (int ks = 0; ks < 4; ks++) {
            const int k0 = ks * 8;
            uint32_t a[4][4];
            #pragma unroll
            for (int mi = 0; mi < 4; mi++) {
                const int base = (warp_m * 64 + mi * 16 + lr) * AST + k0 + lc;
                a[mi][0] = __float_as_uint(As[base]);
                a[mi][1] = __float_as_uint(As[base + 8 * AST]);
                a[mi][2] = __float_as_uint(As[base + 4]);
                a[mi][3] = __float_as_uint(As[base + 8 * AST + 4]);
            }
            uint32_t b[8][2];
            #pragma unroll
            for (int ni = 0; ni < 8; ni++) {
                const int base = (k0 + lc) * BST + warp_n * 64 + ni * 8 + lr;
                b[ni][0] = __float_as_uint(Bs[base]);
                b[ni][1] = __float_as_uint(Bs[base + 4 * BST]);
            }
            #pragma unroll
            for (int mi = 0; mi < 4; mi++)
                #pragma unroll
                for (int ni = 0; ni < 8; ni++)
                    mma_tf32(acc[mi][ni], a[mi], b[ni]);
        }

        if (++buf == NSTAGE) buf = 0;
    }

    // Epilogue
    #pragma unroll
    for (int mi = 0; mi < 4; mi++) {
        #pragma unroll
        for (int ni = 0; ni < 8; ni++) {
            const int r0 = brow + warp_m * 64 + mi * 16 + lr;
            const int c0 = bcol + warp_n * 64 + ni * 8 + lc * 2;
            *(float2*)(C + (size_t)r0 * N + c0)       = make_float2(acc[mi][ni][0], acc[mi][ni][1]);
            *(float2*)(C + (size_t)(r0 + 8) * N + c0) = make_float2(acc[mi][ni][2], acc[mi][ni][3]);
        }
    }
}

// ---------------------------------------------------------------------------
// Elementwise tf32 rounding (float4 vectorized)
// ---------------------------------------------------------------------------
__global__ void cvt_tf32_kernel(const float* __restrict__ in, float* __restrict__ out,
                                size_t n4) {
    size_t i = (size_t)blockIdx.x * blockDim.x + threadIdx.x;
    if (i >= n4) return;
    float4 v = ((const float4*)in)[i];
    v.x = f2tf32(v.x); v.y = f2tf32(v.y); v.z = f2tf32(v.z); v.w = f2tf32(v.w);
    ((float4*)out)[i] = v;
}

// ---------------------------------------------------------------------------
// Fused: Bx = B_gate*x_proj; causal L=3 depthwise conv; y = tf32(C_gate*conv)
// ---------------------------------------------------------------------------
__global__ void conv_gate_kernel(const float* __restrict__ conv_w,
                                 float* __restrict__ y) {
    const size_t total = (size_t)BB * SS * (DD / 4);
    size_t idx = (size_t)blockIdx.x * blockDim.x + threadIdx.x;
    if (idx >= total) return;

    const int    d4 = (int)(idx % (DD / 4));
    const size_t bs = idx / (DD / 4);
    const int    s  = (int)(bs % SS);
    const int    d  = d4 * 4;

    const float* bse = g_BCx + bs * TRIPLE;
    const float* bm1 = bse - TRIPLE;
    const float* bm2 = bse - 2 * TRIPLE;

    float out[4];
    #pragma unroll
    for (int j = 0; j < 4; j++) {
        const int dj = d + j;
        const float w0 = conv_w[dj * LL + 0];
        const float w1 = conv_w[dj * LL + 1];
        const float w2 = conv_w[dj * LL + 2];

        float bx_s  = bse[dj] * bse[2 * DD + dj];
        float bx_s1 = (s >= 1) ? bm1[dj] * bm1[2 * DD + dj] : 0.0f;
        float bx_s2 = (s >= 2) ? bm2[dj] * bm2[2 * DD + dj] : 0.0f;

        float conv = w2 * bx_s + w1 * bx_s1 + w0 * bx_s2;
        out[j] = f2tf32(bse[DD + dj] * conv);
    }
    *(float4*)(g_y + bs * DD + d) = *(float4*)out;
}

// ---------------------------------------------------------------------------
extern "C" void kernel_launch(void* const* d_in, const int* in_sizes, int n_in,
                              void* d_out, int out_size) {
    const float* x      = (const float*)d_in[0];
    const float* W_in   = (const float*)d_in[1];
    const float* conv_w = (const float*)d_in[2];
    const float* W_out  = (const float*)d_in[3];
    float*       out    = (float*)d_out;

    float *BCx, *y, *xc, *Win, *Wout;
    cudaGetSymbolAddress((void**)&BCx,  g_BCx);
    cudaGetSymbolAddress((void**)&y,    g_y);
    cudaGetSymbolAddress((void**)&xc,   g_xc);
    cudaGetSymbolAddress((void**)&Win,  g_Win);
    cudaGetSymbolAddress((void**)&Wout, g_Wout);

    cudaFuncSetAttribute(tf32_gemm, cudaFuncAttributeMaxDynamicSharedMemorySize, SMEM_BYTES);

    // Pre-round inputs to tf32 (rna) into scratch
    {
        size_t n4;
        n4 = (size_t)MTOT * DD / 4;
        cvt_tf32_kernel<<<(unsigned)((n4 + 255) / 256), 256>>>(x, xc, n4);
        n4 = (size_t)DD * TRIPLE / 4;
        cvt_tf32_kernel<<<(unsigned)((n4 + 255) / 256), 256>>>(W_in, Win, n4);
        n4 = (size_t)DD * DD / 4;
        cvt_tf32_kernel<<<(unsigned)((n4 + 255) / 256), 256>>>(W_out, Wout, n4);
    }

    // GEMM1: BCx = x' @ W_in'   (16384 x 2048) @ (2048 x 6144)
    tf32_gemm<<<dim3(TRIPLE / BN, MTOT / BM), 128, SMEM_BYTES>>>(xc, Win, BCx, TRIPLE, DD);

    // Conv + gates -> y (tf32-rounded)
    {
        size_t total = (size_t)BB * SS * (DD / 4);
        conv_gate_kernel<<<(unsigned)((total + 255) / 256), 256>>>(conv_w, y);
    }

    // GEMM2: out = y @ W_out'   (16384 x 2048) @ (2048 x 2048)
    tf32_gemm<<<dim3(DD / BN, MTOT / BM), 128, SMEM_BYTES>>>(y, Wout, out, DD, DD);
}